// round 9
// baseline (speedup 1.0000x reference)
#include <cuda_runtime.h>
#include <math.h>
#include <stdint.h>

#define D    128
#define NN   50000
#define EE   1600000
#define RR   8
#define LL   3
#define NB   (RR*NN)
#define SCAN_BLK 391    /* ceil(NB/1024) */
#define KTOT 1152       /* 8*128 relation means + 128 root */
#define NCH  36         /* KTOT / 32 */
#define SROW 40         /* smem row stride in uint16 (80B, conflict-free) */
#define PLANEB (128*SROW*2)   /* 10240 B per plane */
#define STAGE2B (4*PLANEB)    /* Ahi+Alo+Bhi+Blo = 40960 B */
#define GDSM  (2*STAGE2B)     /* 81920 */

// ---------------- scratch (static device arrays; no allocation) ----------------
__device__ float    g_hA[NN*D];               // ping
__device__ float    g_hB[NN*D];               // pong
__device__ uint16_t g_Ahi[(size_t)NN*KTOT];   // A operand bf16 hi plane
__device__ uint16_t g_Alo[(size_t)NN*KTOT];   // A operand bf16 lo plane
__device__ uint16_t g_Bthi[LL*D*KTOT];        // weights bf16 hi [l][f][k]
__device__ uint16_t g_Btlo[LL*D*KTOT];        // weights bf16 lo
__device__ float    g_invc[NB];
__device__ int      g_cnt[NB];
__device__ int      g_boff[NB+1];
__device__ int      g_bcur[NB];
__device__ int      g_srcs[EE];
__device__ int      g_sync[SCAN_BLK+1];       // [0..SCAN_BLK): flags, [SCAN_BLK]: bid counter
__device__ int      g_sagg[SCAN_BLK];
__device__ int      g_sinc[SCAN_BLK];

// ---------------- helpers ----------------
__device__ __forceinline__ uint32_t su32(const void* p) {
    uint32_t a;
    asm("{.reg .u64 t; cvta.to.shared.u64 t, %1; cvt.u32.u64 %0, t;}" : "=r"(a) : "l"(p));
    return a;
}
__device__ __forceinline__ void cp16(uint32_t s, const void* g) {
    asm volatile("cp.async.cg.shared.global [%0], [%1], 16;" :: "r"(s), "l"(g));
}
// split (v0,v1) into packed bf16x2 hi and lo (elem k in low half, k+1 in high)
__device__ __forceinline__ void bsplit2(float v0, float v1, uint32_t& hi, uint32_t& lo) {
    asm("cvt.rn.bf16x2.f32 %0, %1, %2;" : "=r"(hi) : "f"(v1), "f"(v0));
    float h0 = __uint_as_float(hi << 16);
    float h1 = __uint_as_float(hi & 0xffff0000u);
    float l0 = v0 - h0, l1 = v1 - h1;
    asm("cvt.rn.bf16x2.f32 %0, %1, %2;" : "=r"(lo) : "f"(l1), "f"(l0));
}
__device__ __forceinline__ void mma_bf16(float* c, const uint32_t* a, const uint32_t* b) {
    asm volatile(
        "mma.sync.aligned.m16n8k16.row.col.f32.bf16.bf16.f32 "
        "{%0,%1,%2,%3},{%4,%5,%6,%7},{%8,%9},{%0,%1,%2,%3};"
        : "+f"(c[0]), "+f"(c[1]), "+f"(c[2]), "+f"(c[3])
        : "r"(a[0]), "r"(a[1]), "r"(a[2]), "r"(a[3]), "r"(b[0]), "r"(b[1]));
}

// ------- kernel 1: edge count + node gather + weight split-prep (one grid) -------
__global__ void k_count_gather_prep(const int* __restrict__ et, const int* __restrict__ dst,
                                    const int* __restrict__ x, const float* __restrict__ emb,
                                    const float* __restrict__ w_rel, const float* __restrict__ w_root) {
    int b = blockIdx.x;
    if (b < 6250) {
        int e = b*256 + threadIdx.x;
        if (e < EE) atomicAdd(&g_cnt[et[e]*NN + dst[e]], 1);
    } else if (b < 12500) {
        int i = (b - 6250)*256 + threadIdx.x;
        if (i < NN*32) {
            int row = i >> 5, c = i & 31;
            ((float4*)g_hA)[i] = ((const float4*)emb)[(long long)x[row]*32 + c];
        }
    } else {
        int i = (b - 12500)*256 + threadIdx.x;
        if (i >= LL*D*KTOT) return;
        int l = i / (D*KTOT);
        int rem = i - l*D*KTOT;
        int f = rem / KTOT;
        int k = rem - f*KTOT;
        float v;
        if (k < RR*D) {
            int r = k >> 7, dd = k & 127;
            v = w_rel[(((size_t)(l*RR + r))*D + dd)*D + f];
        } else {
            int dd = k - RR*D;
            v = w_root[((size_t)l*D + dd)*D + f];
        }
        uint32_t hb;
        asm("cvt.rn.bf16x2.f32 %0, %1, %2;" : "=r"(hb) : "f"(0.f), "f"(v));
        float hf = __uint_as_float(hb << 16);
        float lf = v - hf;
        uint32_t lb;
        asm("cvt.rn.bf16x2.f32 %0, %1, %2;" : "=r"(lb) : "f"(0.f), "f"(lf));
        g_Bthi[i] = (uint16_t)(hb & 0xffff);
        g_Btlo[i] = (uint16_t)(lb & 0xffff);
    }
}

// ------- kernel 2: single-pass decoupled-lookback scan (boff/bcur/invc) ---------
__global__ void k_scan() {
    __shared__ int s_bid, s_excl;
    __shared__ int ws[8];
    int t = threadIdx.x;
    if (t == 0) s_bid = atomicAdd(&g_sync[SCAN_BLK], 1);
    __syncthreads();
    int bid = s_bid;
    int base = bid*1024 + t*4;
    int c[4]; int tsum = 0;
    #pragma unroll
    for (int j = 0; j < 4; j++) { int i = base + j; c[j] = (i < NB) ? g_cnt[i] : 0; tsum += c[j]; }
    int x = tsum;
    int lane = t & 31, wid = t >> 5;
    #pragma unroll
    for (int o = 1; o < 32; o <<= 1) { int y = __shfl_up_sync(0xffffffffu, x, o); if (lane >= o) x += y; }
    if (lane == 31) ws[wid] = x;
    __syncthreads();
    if (t == 0) {
        int tot = 0;
        #pragma unroll
        for (int w = 0; w < 8; w++) tot += ws[w];
        g_sagg[bid] = tot;
        __threadfence();
        atomicExch(&g_sync[bid], 1);
        int excl = 0;
        for (int j = bid - 1; j >= 0; ) {
            int f;
            do { f = atomicAdd(&g_sync[j], 0); } while (f == 0);
            if (f == 2) { excl += atomicAdd(&g_sinc[j], 0); break; }
            excl += atomicAdd(&g_sagg[j], 0);
            j--;
        }
        g_sinc[bid] = excl + tot;
        __threadfence();
        atomicExch(&g_sync[bid], 2);
        s_excl = excl;
        if (bid == 0) g_boff[NB] = EE;
    }
    __syncthreads();
    int pre = s_excl;
    for (int w = 0; w < wid; w++) pre += ws[w];
    int off = pre + x - tsum;
    #pragma unroll
    for (int j = 0; j < 4; j++) {
        int i = base + j;
        if (i < NB) {
            g_boff[i] = off; g_bcur[i] = off; off += c[j];
            g_invc[i] = 1.0f / fmaxf((float)c[j], 1.0f);
        }
    }
}

// ------- kernel 3: partition edges by (relation,dst) bucket ----------------------
__global__ void k_partition(const int* __restrict__ src, const int* __restrict__ dst,
                            const int* __restrict__ et) {
    int e = blockIdx.x*blockDim.x + threadIdx.x;
    if (e < EE) {
        int b = et[e]*NN + dst[e];
        int p = atomicAdd(&g_bcur[b], 1);
        g_srcs[p] = src[e];
    }
}

// ------- kernel 4 (profiled): 8 relation means + root -> split bf16 planes -------
__global__ void k_agg(const float* __restrict__ h) {
    int n = blockIdx.x;
    int wid = threadIdx.x >> 5, lane = threadIdx.x & 31;
    int b = wid*NN + n;
    int beg = g_boff[b], end = g_boff[b+1];
    float4 acc = make_float4(0.f, 0.f, 0.f, 0.f);
    int e = beg;
    for (; e + 4 <= end; e += 4) {
        int s0 = g_srcs[e], s1 = g_srcs[e+1], s2 = g_srcs[e+2], s3 = g_srcs[e+3];
        float4 v0 = __ldg((const float4*)&h[(size_t)s0*D + lane*4]);
        float4 v1 = __ldg((const float4*)&h[(size_t)s1*D + lane*4]);
        float4 v2 = __ldg((const float4*)&h[(size_t)s2*D + lane*4]);
        float4 v3 = __ldg((const float4*)&h[(size_t)s3*D + lane*4]);
        acc.x += v0.x + v1.x + v2.x + v3.x;
        acc.y += v0.y + v1.y + v2.y + v3.y;
        acc.z += v0.z + v1.z + v2.z + v3.z;
        acc.w += v0.w + v1.w + v2.w + v3.w;
    }
    for (; e < end; e++) {
        int s = g_srcs[e];
        float4 v = __ldg((const float4*)&h[(size_t)s*D + lane*4]);
        acc.x += v.x; acc.y += v.y; acc.z += v.z; acc.w += v.w;
    }
    float sc = g_invc[b];
    acc.x *= sc; acc.y *= sc; acc.z *= sc; acc.w *= sc;
    uint32_t h0, l0, h1, l1;
    bsplit2(acc.x, acc.y, h0, l0);
    bsplit2(acc.z, acc.w, h1, l1);
    size_t idx = (size_t)n*KTOT + wid*D + lane*4;
    *(uint2*)&g_Ahi[idx] = make_uint2(h0, h1);
    *(uint2*)&g_Alo[idx] = make_uint2(l0, l1);
    if (threadIdx.x < 32) {
        float4 v = __ldg((const float4*)&h[(size_t)n*D + threadIdx.x*4]);
        bsplit2(v.x, v.y, h0, l0);
        bsplit2(v.z, v.w, h1, l1);
        size_t ridx = (size_t)n*KTOT + RR*D + threadIdx.x*4;
        *(uint2*)&g_Ahi[ridx] = make_uint2(h0, h1);
        *(uint2*)&g_Alo[ridx] = make_uint2(l0, l1);
    }
}

// ---------------- bf16x3 mma GEMM + fused bias/LN/ReLU/residual ----------------
__global__ void __launch_bounds__(256, 1) k_gemm_ln(
    const uint16_t* __restrict__ Bhi, const uint16_t* __restrict__ Blo,
    const float* __restrict__ bias, const float* __restrict__ gamma,
    const float* __restrict__ beta, const float* __restrict__ hprev,
    float* __restrict__ dst)
{
    extern __shared__ float smf[];
    uint16_t* sm16 = (uint16_t*)smf;
    int tid = threadIdx.x, wid = tid >> 5, lane = tid & 31;
    int row0 = blockIdx.x * 128;
    int warp_m = (wid >> 2) * 64;       // 0 or 64
    int warp_n = (wid & 3) * 32;        // 0,32,64,96
    int grp = lane >> 2, qid = lane & 3;
    uint32_t sbase = su32(smf);

    float c[4][4][4];
    #pragma unroll
    for (int i = 0; i < 4; i++)
        #pragma unroll
        for (int j = 0; j < 4; j++)
            #pragma unroll
            for (int q = 0; q < 4; q++) c[i][j][q] = 0.f;

    auto load_chunk = [&](int it, int s) {
        const int kb = it * 32;
        uint32_t st = sbase + (uint32_t)s*STAGE2B;
        #pragma unroll
        for (int j = 0; j < 2; j++) {
            int slot = tid + j*256;           // 0..511
            int row = slot >> 2, seg = slot & 3;
            uint32_t soff = (uint32_t)(row*(SROW*2) + seg*16);
            int gm = row0 + row; if (gm >= NN) gm = NN - 1;   // clamp (never stored)
            size_t ga = (size_t)gm*KTOT + kb + seg*8;
            size_t gb = (size_t)row*KTOT + kb + seg*8;
            cp16(st + soff,             g_Ahi + ga);
            cp16(st + PLANEB + soff,    g_Alo + ga);
            cp16(st + 2*PLANEB + soff,  Bhi + gb);
            cp16(st + 3*PLANEB + soff,  Blo + gb);
        }
        asm volatile("cp.async.commit_group;" ::: "memory");
    };

    load_chunk(0, 0);
    load_chunk(1, 1);

    for (int it = 0; it < NCH; it++) {
        int s = it & 1;
        if (it < NCH-1) asm volatile("cp.async.wait_group 1;" ::: "memory");
        else            asm volatile("cp.async.wait_group 0;" ::: "memory");
        __syncthreads();
        const uint16_t* Ahs = sm16 + s*(STAGE2B/2);
        const uint16_t* Als = Ahs + PLANEB/2;
        const uint16_t* Bhs = Ahs + PLANEB;
        const uint16_t* Bls = Ahs + 3*(PLANEB/2);
        #pragma unroll
        for (int kk = 0; kk < 32; kk += 16) {
            uint32_t ah[4][4], al[4][4], bh[4][2], bl[4][2];
            int ka = kk + 2*qid;
            #pragma unroll
            for (int i = 0; i < 4; i++) {
                int r = warp_m + i*16 + grp;
                ah[i][0] = *(const uint32_t*)&Ahs[r*SROW + ka];
                ah[i][1] = *(const uint32_t*)&Ahs[(r+8)*SROW + ka];
                ah[i][2] = *(const uint32_t*)&Ahs[r*SROW + ka + 8];
                ah[i][3] = *(const uint32_t*)&Ahs[(r+8)*SROW + ka + 8];
                al[i][0] = *(const uint32_t*)&Als[r*SROW + ka];
                al[i][1] = *(const uint32_t*)&Als[(r+8)*SROW + ka];
                al[i][2] = *(const uint32_t*)&Als[r*SROW + ka + 8];
                al[i][3] = *(const uint32_t*)&Als[(r+8)*SROW + ka + 8];
            }
            #pragma unroll
            for (int j = 0; j < 4; j++) {
                int nrow = warp_n + j*8 + grp;
                bh[j][0] = *(const uint32_t*)&Bhs[nrow*SROW + ka];
                bh[j][1] = *(const uint32_t*)&Bhs[nrow*SROW + ka + 8];
                bl[j][0] = *(const uint32_t*)&Bls[nrow*SROW + ka];
                bl[j][1] = *(const uint32_t*)&Bls[nrow*SROW + ka + 8];
            }
            #pragma unroll
            for (int i = 0; i < 4; i++)
                #pragma unroll
                for (int j = 0; j < 4; j++) {
                    mma_bf16(c[i][j], al[i], bh[j]);
                    mma_bf16(c[i][j], ah[i], bl[j]);
                    mma_bf16(c[i][j], ah[i], bh[j]);
                }
        }
        __syncthreads();
        if (it + 2 < NCH) load_chunk(it + 2, s);
    }

    // ---- fused epilogue: bias + LayerNorm + ReLU + residual ----
    float* redSum = smf;            // [128][4]
    float* redSq  = smf + 512;      // [128][4]
    float* s_mu   = smf + 1024;     // [128]
    float* s_rs   = smf + 1152;     // [128]
    int wn = wid & 3;

    float2 gset[4], bset[4];
    #pragma unroll
    for (int j = 0; j < 4; j++) {
        int col = warp_n + j*8 + qid*2;
        gset[j] = *(const float2*)&gamma[col];
        bset[j] = *(const float2*)&beta[col];
    }
    #pragma unroll
    for (int i = 0; i < 4; i++) {
        float s0 = 0.f, q0 = 0.f, s1 = 0.f, q1 = 0.f;
        #pragma unroll
        for (int j = 0; j < 4; j++) {
            int col = warp_n + j*8 + qid*2;
            float bx = bias[col], by = bias[col+1];
            c[i][j][0] += bx; c[i][j][1] += by;
            c[i][j][2] += bx; c[i][j][3] += by;
            s0 += c[i][j][0] + c[i][j][1];
            q0 += c[i][j][0]*c[i][j][0] + c[i][j][1]*c[i][j][1];
            s1 += c[i][j][2] + c[i][j][3];
            q1 += c[i][j][2]*c[i][j][2] + c[i][j][3]*c[i][j][3];
        }
        #pragma unroll
        for (int o = 1; o <= 2; o <<= 1) {
            s0 += __shfl_xor_sync(0xffffffffu, s0, o);
            q0 += __shfl_xor_sync(0xffffffffu, q0, o);
            s1 += __shfl_xor_sync(0xffffffffu, s1, o);
            q1 += __shfl_xor_sync(0xffffffffu, q1, o);
        }
        if (qid == 0) {
            int r0 = warp_m + i*16 + grp;
            redSum[r0*4 + wn] = s0;  redSq[r0*4 + wn] = q0;
            redSum[(r0+8)*4 + wn] = s1;  redSq[(r0+8)*4 + wn] = q1;
        }
    }
    __syncthreads();
    if (tid < 128) {
        float s = redSum[tid*4+0] + redSum[tid*4+1] + redSum[tid*4+2] + redSum[tid*4+3];
        float q = redSq[tid*4+0] + redSq[tid*4+1] + redSq[tid*4+2] + redSq[tid*4+3];
        float mu = s * (1.0f/D);
        float var = q * (1.0f/D) - mu*mu;
        s_mu[tid] = mu;
        s_rs[tid] = rsqrtf(var + 1e-5f);
    }
    __syncthreads();

    #pragma unroll
    for (int i = 0; i < 4; i++) {
        int lr0 = warp_m + i*16 + grp;
        int lr1 = lr0 + 8;
        float mu0 = s_mu[lr0], rs0 = s_rs[lr0];
        float mu1 = s_mu[lr1], rs1 = s_rs[lr1];
        int gm0 = row0 + lr0, gm1 = row0 + lr1;
        #pragma unroll
        for (int j = 0; j < 4; j++) {
            int col = warp_n + j*8 + qid*2;
            if (gm0 < NN) {
                float y0 = fmaxf((c[i][j][0]-mu0)*rs0*gset[j].x + bset[j].x, 0.f);
                float y1 = fmaxf((c[i][j][1]-mu0)*rs0*gset[j].y + bset[j].y, 0.f);
                if (hprev) {
                    const float2 p = *(const float2*)&hprev[(size_t)gm0*D + col];
                    y0 += p.x; y1 += p.y;
                }
                *(float2*)&dst[(size_t)gm0*D + col] = make_float2(y0, y1);
            }
            if (gm1 < NN) {
                float y0 = fmaxf((c[i][j][2]-mu1)*rs1*gset[j].x + bset[j].x, 0.f);
                float y1 = fmaxf((c[i][j][3]-mu1)*rs1*gset[j].y + bset[j].y, 0.f);
                if (hprev) {
                    const float2 p = *(const float2*)&hprev[(size_t)gm1*D + col];
                    y0 += p.x; y1 += p.y;
                }
                *(float2*)&dst[(size_t)gm1*D + col] = make_float2(y0, y1);
            }
        }
    }
}

// ---------------- launcher ----------------
extern "C" void kernel_launch(void* const* d_in, const int* in_sizes, int n_in,
                              void* d_out, int out_size)
{
    const int*   x      = (const int*)d_in[0];
    const int*   ei     = (const int*)d_in[1];
    const int*   et     = (const int*)d_in[2];
    const float* emb    = (const float*)d_in[3];
    const float* w_rel  = (const float*)d_in[4];
    const float* w_root = (const float*)d_in[5];
    const float* bias   = (const float*)d_in[6];
    const float* gamma  = (const float*)d_in[7];
    const float* beta   = (const float*)d_in[8];
    float* out = (float*)d_out;
    const int* src = ei;
    const int* dst = ei + EE;

    float *hA, *hB;
    uint16_t *Bthi, *Btlo;
    int *cntp, *syncp;
    cudaGetSymbolAddress((void**)&hA,    g_hA);
    cudaGetSymbolAddress((void**)&hB,    g_hB);
    cudaGetSymbolAddress((void**)&Bthi,  g_Bthi);
    cudaGetSymbolAddress((void**)&Btlo,  g_Btlo);
    cudaGetSymbolAddress((void**)&cntp,  g_cnt);
    cudaGetSymbolAddress((void**)&syncp, g_sync);

    cudaFuncSetAttribute(k_gemm_ln, cudaFuncAttributeMaxDynamicSharedMemorySize, GDSM);

    cudaMemsetAsync(cntp,  0, (size_t)NB*sizeof(int));
    cudaMemsetAsync(syncp, 0, (SCAN_BLK+1)*sizeof(int));
    const int PREP_BLK = (LL*D*KTOT + 255)/256;          // 1728
    k_count_gather_prep<<<12500 + PREP_BLK, 256>>>(et, dst, x, emb, w_rel, w_root); // k1
    k_scan<<<SCAN_BLK, 256>>>();                         // k2
    k_partition<<<6250, 256>>>(src, dst, et);            // k3
    const int GB = (NN + 127) / 128;                     // 391 tiles
    const size_t LW = (size_t)D*KTOT;
    // layer 0: hA -> hB; layer 1: hB -> hA (+hB); layer 2: hA -> out (+hA)
    k_agg<<<NN, 256>>>(hA);                              // k4 <- profiled
    k_gemm_ln<<<GB, 256, GDSM>>>(Bthi,        Btlo,        bias,       gamma,       beta,       nullptr, hB);
    k_agg<<<NN, 256>>>(hB);
    k_gemm_ln<<<GB, 256, GDSM>>>(Bthi + LW,   Btlo + LW,   bias + D,   gamma + D,   beta + D,   hB,      hA);
    k_agg<<<NN, 256>>>(hA);
    k_gemm_ln<<<GB, 256, GDSM>>>(Bthi + 2*LW, Btlo + 2*LW, bias + 2*D, gamma + 2*D, beta + 2*D, hA,      out);
}

// round 10
// speedup vs baseline: 1.0110x; 1.0110x over previous
#include <cuda_runtime.h>
#include <math.h>
#include <stdint.h>

#define D    128
#define NN   50000
#define EE   1600000
#define RR   8
#define LL   3
#define NB   (RR*NN)
#define SCAN_BLK 391    /* ceil(NB/1024) */
#define KTOT 1152       /* 8*128 relation means + 128 root */
#define NCH  36         /* KTOT / 32 */
#define SROW 40         /* smem row stride in uint16 (80B, conflict-free) */
#define PLANEB (128*SROW*2)   /* 10240 B per plane */
#define STAGE2B (4*PLANEB)    /* Ahi+Alo+Bhi+Blo = 40960 B */
#define NSTG  3
#define GDSM  (NSTG*STAGE2B)  /* 122880 */

// ---------------- scratch (static device arrays; no allocation) ----------------
__device__ float    g_hA[NN*D];               // ping
__device__ float    g_hB[NN*D];               // pong
__device__ uint16_t g_Ahi[(size_t)NN*KTOT];   // A operand bf16 hi plane
__device__ uint16_t g_Alo[(size_t)NN*KTOT];   // A operand bf16 lo plane
__device__ uint16_t g_Bthi[LL*D*KTOT];        // weights bf16 hi [l][f][k]
__device__ uint16_t g_Btlo[LL*D*KTOT];        // weights bf16 lo
__device__ float    g_invc[NB];
__device__ int      g_cnt[NB];
__device__ int      g_boff[NB+1];
__device__ int      g_bcur[NB];
__device__ int      g_srcs[EE];
__device__ int      g_sync[SCAN_BLK+1];       // [0..SCAN_BLK): flags, [SCAN_BLK]: bid counter
__device__ int      g_sagg[SCAN_BLK];
__device__ int      g_sinc[SCAN_BLK];

// ---------------- helpers ----------------
__device__ __forceinline__ uint32_t su32(const void* p) {
    uint32_t a;
    asm("{.reg .u64 t; cvta.to.shared.u64 t, %1; cvt.u32.u64 %0, t;}" : "=r"(a) : "l"(p));
    return a;
}
__device__ __forceinline__ void cp16(uint32_t s, const void* g) {
    asm volatile("cp.async.cg.shared.global [%0], [%1], 16;" :: "r"(s), "l"(g));
}
__device__ __forceinline__ void ldsm4(uint32_t& r0, uint32_t& r1, uint32_t& r2, uint32_t& r3,
                                      uint32_t addr) {
    asm volatile("ldmatrix.sync.aligned.m8n8.x4.shared.b16 {%0,%1,%2,%3}, [%4];"
                 : "=r"(r0), "=r"(r1), "=r"(r2), "=r"(r3) : "r"(addr));
}
// split (v0,v1) into packed bf16x2 hi and lo (elem k in low half, k+1 in high)
__device__ __forceinline__ void bsplit2(float v0, float v1, uint32_t& hi, uint32_t& lo) {
    asm("cvt.rn.bf16x2.f32 %0, %1, %2;" : "=r"(hi) : "f"(v1), "f"(v0));
    float h0 = __uint_as_float(hi << 16);
    float h1 = __uint_as_float(hi & 0xffff0000u);
    float l0 = v0 - h0, l1 = v1 - h1;
    asm("cvt.rn.bf16x2.f32 %0, %1, %2;" : "=r"(lo) : "f"(l1), "f"(l0));
}
__device__ __forceinline__ void mma_bf16(float* c, const uint32_t* a, const uint32_t* b) {
    asm volatile(
        "mma.sync.aligned.m16n8k16.row.col.f32.bf16.bf16.f32 "
        "{%0,%1,%2,%3},{%4,%5,%6,%7},{%8,%9},{%0,%1,%2,%3};"
        : "+f"(c[0]), "+f"(c[1]), "+f"(c[2]), "+f"(c[3])
        : "r"(a[0]), "r"(a[1]), "r"(a[2]), "r"(a[3]), "r"(b[0]), "r"(b[1]));
}

// ------- kernel 1: edge count + node gather + weight split-prep (one grid) -------
__global__ void k_count_gather_prep(const int* __restrict__ et, const int* __restrict__ dst,
                                    const int* __restrict__ x, const float* __restrict__ emb,
                                    const float* __restrict__ w_rel, const float* __restrict__ w_root) {
    int b = blockIdx.x;
    if (b < 6250) {
        int e = b*256 + threadIdx.x;
        if (e < EE) atomicAdd(&g_cnt[et[e]*NN + dst[e]], 1);
    } else if (b < 12500) {
        int i = (b - 6250)*256 + threadIdx.x;
        if (i < NN*32) {
            int row = i >> 5, c = i & 31;
            ((float4*)g_hA)[i] = ((const float4*)emb)[(long long)x[row]*32 + c];
        }
    } else {
        int i = (b - 12500)*256 + threadIdx.x;
        if (i >= LL*D*KTOT) return;
        int l = i / (D*KTOT);
        int rem = i - l*D*KTOT;
        int f = rem / KTOT;
        int k = rem - f*KTOT;
        float v;
        if (k < RR*D) {
            int r = k >> 7, dd = k & 127;
            v = w_rel[(((size_t)(l*RR + r))*D + dd)*D + f];
        } else {
            int dd = k - RR*D;
            v = w_root[((size_t)l*D + dd)*D + f];
        }
        uint32_t hb;
        asm("cvt.rn.bf16x2.f32 %0, %1, %2;" : "=r"(hb) : "f"(0.f), "f"(v));
        float hf = __uint_as_float(hb << 16);
        float lf = v - hf;
        uint32_t lb;
        asm("cvt.rn.bf16x2.f32 %0, %1, %2;" : "=r"(lb) : "f"(0.f), "f"(lf));
        g_Bthi[i] = (uint16_t)(hb & 0xffff);
        g_Btlo[i] = (uint16_t)(lb & 0xffff);
    }
}

// ------- kernel 2: single-pass decoupled-lookback scan (boff/bcur/invc) ---------
__global__ void k_scan() {
    __shared__ int s_bid, s_excl;
    __shared__ int ws[8];
    int t = threadIdx.x;
    if (t == 0) s_bid = atomicAdd(&g_sync[SCAN_BLK], 1);
    __syncthreads();
    int bid = s_bid;
    int base = bid*1024 + t*4;
    int c[4]; int tsum = 0;
    #pragma unroll
    for (int j = 0; j < 4; j++) { int i = base + j; c[j] = (i < NB) ? g_cnt[i] : 0; tsum += c[j]; }
    int x = tsum;
    int lane = t & 31, wid = t >> 5;
    #pragma unroll
    for (int o = 1; o < 32; o <<= 1) { int y = __shfl_up_sync(0xffffffffu, x, o); if (lane >= o) x += y; }
    if (lane == 31) ws[wid] = x;
    __syncthreads();
    if (t == 0) {
        int tot = 0;
        #pragma unroll
        for (int w = 0; w < 8; w++) tot += ws[w];
        g_sagg[bid] = tot;
        __threadfence();
        atomicExch(&g_sync[bid], 1);
        int excl = 0;
        for (int j = bid - 1; j >= 0; ) {
            int f;
            do { f = atomicAdd(&g_sync[j], 0); } while (f == 0);
            if (f == 2) { excl += atomicAdd(&g_sinc[j], 0); break; }
            excl += atomicAdd(&g_sagg[j], 0);
            j--;
        }
        g_sinc[bid] = excl + tot;
        __threadfence();
        atomicExch(&g_sync[bid], 2);
        s_excl = excl;
        if (bid == 0) g_boff[NB] = EE;
    }
    __syncthreads();
    int pre = s_excl;
    for (int w = 0; w < wid; w++) pre += ws[w];
    int off = pre + x - tsum;
    #pragma unroll
    for (int j = 0; j < 4; j++) {
        int i = base + j;
        if (i < NB) {
            g_boff[i] = off; g_bcur[i] = off; off += c[j];
            g_invc[i] = 1.0f / fmaxf((float)c[j], 1.0f);
        }
    }
}

// ------- kernel 3: partition edges by (relation,dst) bucket ----------------------
__global__ void k_partition(const int* __restrict__ src, const int* __restrict__ dst,
                            const int* __restrict__ et) {
    int e = blockIdx.x*blockDim.x + threadIdx.x;
    if (e < EE) {
        int b = et[e]*NN + dst[e];
        int p = atomicAdd(&g_bcur[b], 1);
        g_srcs[p] = src[e];
    }
}

// ------- kernel 4 (profiled): 8 relation means + root -> split bf16 planes -------
__global__ void k_agg(const float* __restrict__ h) {
    int n = blockIdx.x;
    int wid = threadIdx.x >> 5, lane = threadIdx.x & 31;
    int b = wid*NN + n;
    int beg = g_boff[b], end = g_boff[b+1];
    float4 acc = make_float4(0.f, 0.f, 0.f, 0.f);
    int e = beg;
    for (; e + 4 <= end; e += 4) {
        int s0 = g_srcs[e], s1 = g_srcs[e+1], s2 = g_srcs[e+2], s3 = g_srcs[e+3];
        float4 v0 = *(const float4*)&h[(size_t)s0*D + lane*4];
        float4 v1 = *(const float4*)&h[(size_t)s1*D + lane*4];
        float4 v2 = *(const float4*)&h[(size_t)s2*D + lane*4];
        float4 v3 = *(const float4*)&h[(size_t)s3*D + lane*4];
        acc.x += v0.x + v1.x + v2.x + v3.x;
        acc.y += v0.y + v1.y + v2.y + v3.y;
        acc.z += v0.z + v1.z + v2.z + v3.z;
        acc.w += v0.w + v1.w + v2.w + v3.w;
    }
    for (; e < end; e++) {
        int s = g_srcs[e];
        float4 v = *(const float4*)&h[(size_t)s*D + lane*4];
        acc.x += v.x; acc.y += v.y; acc.z += v.z; acc.w += v.w;
    }
    float sc = g_invc[b];
    acc.x *= sc; acc.y *= sc; acc.z *= sc; acc.w *= sc;
    uint32_t h0, l0, h1, l1;
    bsplit2(acc.x, acc.y, h0, l0);
    bsplit2(acc.z, acc.w, h1, l1);
    size_t idx = (size_t)n*KTOT + wid*D + lane*4;
    *(uint2*)&g_Ahi[idx] = make_uint2(h0, h1);
    *(uint2*)&g_Alo[idx] = make_uint2(l0, l1);
    if (threadIdx.x < 32) {
        float4 v = *(const float4*)&h[(size_t)n*D + threadIdx.x*4];
        bsplit2(v.x, v.y, h0, l0);
        bsplit2(v.z, v.w, h1, l1);
        size_t ridx = (size_t)n*KTOT + RR*D + threadIdx.x*4;
        *(uint2*)&g_Ahi[ridx] = make_uint2(h0, h1);
        *(uint2*)&g_Alo[ridx] = make_uint2(l0, l1);
    }
}

// ------- bf16x3 mma GEMM (ldmatrix + 3-stage) + fused bias/LN/ReLU/residual -----
__global__ void __launch_bounds__(256, 1) k_gemm_ln(
    const uint16_t* __restrict__ Bhi, const uint16_t* __restrict__ Blo,
    const float* __restrict__ bias, const float* __restrict__ gamma,
    const float* __restrict__ beta, const float* __restrict__ hprev,
    float* __restrict__ dst)
{
    extern __shared__ float smf[];
    int tid = threadIdx.x, wid = tid >> 5, lane = tid & 31;
    int row0 = blockIdx.x * 128;
    int warp_m = (wid >> 2) * 64;       // 0 or 64
    int warp_n = (wid & 3) * 32;        // 0,32,64,96
    int grp = lane >> 2, qid = lane & 3;
    uint32_t sbase = su32(smf);

    // ldmatrix per-thread offsets (bytes)
    uint32_t aoff = (uint32_t)(((warp_m + (lane & 15))*SROW + ((lane >> 4) << 3)) * 2);
    uint32_t boff = (uint32_t)(((warp_n + ((lane >> 4) << 3) + (lane & 7))*SROW
                                + (((lane >> 3) & 1) << 3)) * 2);

    float c[4][4][4];
    #pragma unroll
    for (int i = 0; i < 4; i++)
        #pragma unroll
        for (int j = 0; j < 4; j++)
            #pragma unroll
            for (int q = 0; q < 4; q++) c[i][j][q] = 0.f;

    auto load_chunk = [&](int it, int s) {
        const int kb = it * 32;
        uint32_t st = sbase + (uint32_t)s*STAGE2B;
        #pragma unroll
        for (int j = 0; j < 2; j++) {
            int slot = tid + j*256;           // 0..511
            int row = slot >> 2, seg = slot & 3;
            uint32_t soff = (uint32_t)(row*(SROW*2) + seg*16);
            int gm = row0 + row; if (gm >= NN) gm = NN - 1;   // clamp (never stored)
            size_t ga = (size_t)gm*KTOT + kb + seg*8;
            size_t gb = (size_t)row*KTOT + kb + seg*8;
            cp16(st + soff,             g_Ahi + ga);
            cp16(st + PLANEB + soff,    g_Alo + ga);
            cp16(st + 2*PLANEB + soff,  Bhi + gb);
            cp16(st + 3*PLANEB + soff,  Blo + gb);
        }
        asm volatile("cp.async.commit_group;" ::: "memory");
    };

    load_chunk(0, 0);
    load_chunk(1, 1);

    for (int it = 0; it < NCH; it++) {
        int s = it % NSTG;
        if (it < NCH-1) asm volatile("cp.async.wait_group 1;" ::: "memory");
        else            asm volatile("cp.async.wait_group 0;" ::: "memory");
        __syncthreads();   // stage s ready; all warps done reading stage (it+2)%3

        if (it + 2 < NCH) load_chunk(it + 2, (it + 2) % NSTG);

        uint32_t st = sbase + (uint32_t)s*STAGE2B;
        #pragma unroll
        for (int kk = 0; kk < 32; kk += 16) {
            uint32_t ah[4][4], al[4][4], bh[4][2], bl[4][2];
            uint32_t aA = st + aoff + (uint32_t)(kk*2);
            uint32_t aB = st + 2*PLANEB + boff + (uint32_t)(kk*2);
            #pragma unroll
            for (int i = 0; i < 4; i++) {
                ldsm4(ah[i][0], ah[i][1], ah[i][2], ah[i][3], aA + (uint32_t)(i*1280));
                ldsm4(al[i][0], al[i][1], al[i][2], al[i][3], aA + PLANEB + (uint32_t)(i*1280));
            }
            ldsm4(bh[0][0], bh[0][1], bh[1][0], bh[1][1], aB);
            ldsm4(bh[2][0], bh[2][1], bh[3][0], bh[3][1], aB + 1280u);
            ldsm4(bl[0][0], bl[0][1], bl[1][0], bl[1][1], aB + PLANEB);
            ldsm4(bl[2][0], bl[2][1], bl[3][0], bl[3][1], aB + PLANEB + 1280u);
            #pragma unroll
            for (int i = 0; i < 4; i++)
                #pragma unroll
                for (int j = 0; j < 4; j++) {
                    mma_bf16(c[i][j], al[i], bh[j]);
                    mma_bf16(c[i][j], ah[i], bl[j]);
                    mma_bf16(c[i][j], ah[i], bh[j]);
                }
        }
    }
    __syncthreads();

    // ---- fused epilogue: bias + LayerNorm + ReLU + residual ----
    float* redSum = smf;            // [128][4]
    float* redSq  = smf + 512;      // [128][4]
    float* s_mu   = smf + 1024;     // [128]
    float* s_rs   = smf + 1152;     // [128]
    int wn = wid & 3;

    float2 gset[4], bset[4];
    #pragma unroll
    for (int j = 0; j < 4; j++) {
        int col = warp_n + j*8 + qid*2;
        gset[j] = *(const float2*)&gamma[col];
        bset[j] = *(const float2*)&beta[col];
    }
    #pragma unroll
    for (int i = 0; i < 4; i++) {
        float s0 = 0.f, q0 = 0.f, s1 = 0.f, q1 = 0.f;
        #pragma unroll
        for (int j = 0; j < 4; j++) {
            int col = warp_n + j*8 + qid*2;
            float bx = bias[col], by = bias[col+1];
            c[i][j][0] += bx; c[i][j][1] += by;
            c[i][j][2] += bx; c[i][j][3] += by;
            s0 += c[i][j][0] + c[i][j][1];
            q0 += c[i][j][0]*c[i][j][0] + c[i][j][1]*c[i][j][1];
            s1 += c[i][j][2] + c[i][j][3];
            q1 += c[i][j][2]*c[i][j][2] + c[i][j][3]*c[i][j][3];
        }
        #pragma unroll
        for (int o = 1; o <= 2; o <<= 1) {
            s0 += __shfl_xor_sync(0xffffffffu, s0, o);
            q0 += __shfl_xor_sync(0xffffffffu, q0, o);
            s1 += __shfl_xor_sync(0xffffffffu, s1, o);
            q1 += __shfl_xor_sync(0xffffffffu, q1, o);
        }
        if (qid == 0) {
            int r0 = warp_m + i*16 + grp;
            redSum[r0*4 + wn] = s0;  redSq[r0*4 + wn] = q0;
            redSum[(r0+8)*4 + wn] = s1;  redSq[(r0+8)*4 + wn] = q1;
        }
    }
    __syncthreads();
    if (tid < 128) {
        float s = redSum[tid*4+0] + redSum[tid*4+1] + redSum[tid*4+2] + redSum[tid*4+3];
        float q = redSq[tid*4+0] + redSq[tid*4+1] + redSq[tid*4+2] + redSq[tid*4+3];
        float mu = s * (1.0f/D);
        float var = q * (1.0f/D) - mu*mu;
        s_mu[tid] = mu;
        s_rs[tid] = rsqrtf(var + 1e-5f);
    }
    __syncthreads();

    #pragma unroll
    for (int i = 0; i < 4; i++) {
        int lr0 = warp_m + i*16 + grp;
        int lr1 = lr0 + 8;
        float mu0 = s_mu[lr0], rs0 = s_rs[lr0];
        float mu1 = s_mu[lr1], rs1 = s_rs[lr1];
        int gm0 = row0 + lr0, gm1 = row0 + lr1;
        #pragma unroll
        for (int j = 0; j < 4; j++) {
            int col = warp_n + j*8 + qid*2;
            if (gm0 < NN) {
                float y0 = fmaxf((c[i][j][0]-mu0)*rs0*gset[j].x + bset[j].x, 0.f);
                float y1 = fmaxf((c[i][j][1]-mu0)*rs0*gset[j].y + bset[j].y, 0.f);
                if (hprev) {
                    const float2 p = *(const float2*)&hprev[(size_t)gm0*D + col];
                    y0 += p.x; y1 += p.y;
                }
                *(float2*)&dst[(size_t)gm0*D + col] = make_float2(y0, y1);
            }
            if (gm1 < NN) {
                float y0 = fmaxf((c[i][j][2]-mu1)*rs1*gset[j].x + bset[j].x, 0.f);
                float y1 = fmaxf((c[i][j][3]-mu1)*rs1*gset[j].y + bset[j].y, 0.f);
                if (hprev) {
                    const float2 p = *(const float2*)&hprev[(size_t)gm1*D + col];
                    y0 += p.x; y1 += p.y;
                }
                *(float2*)&dst[(size_t)gm1*D + col] = make_float2(y0, y1);
            }
        }
    }
}

// ---------------- launcher ----------------
extern "C" void kernel_launch(void* const* d_in, const int* in_sizes, int n_in,
                              void* d_out, int out_size)
{
    const int*   x      = (const int*)d_in[0];
    const int*   ei     = (const int*)d_in[1];
    const int*   et     = (const int*)d_in[2];
    const float* emb    = (const float*)d_in[3];
    const float* w_rel  = (const float*)d_in[4];
    const float* w_root = (const float*)d_in[5];
    const float* bias   = (const float*)d_in[6];
    const float* gamma  = (const float*)d_in[7];
    const float* beta   = (const float*)d_in[8];
    float* out = (float*)d_out;
    const int* src = ei;
    const int* dst = ei + EE;

    float *hA, *hB;
    uint16_t *Bthi, *Btlo;
    int *cntp, *syncp;
    cudaGetSymbolAddress((void**)&hA,    g_hA);
    cudaGetSymbolAddress((void**)&hB,    g_hB);
    cudaGetSymbolAddress((void**)&Bthi,  g_Bthi);
    cudaGetSymbolAddress((void**)&Btlo,  g_Btlo);
    cudaGetSymbolAddress((void**)&cntp,  g_cnt);
    cudaGetSymbolAddress((void**)&syncp, g_sync);

    cudaFuncSetAttribute(k_gemm_ln, cudaFuncAttributeMaxDynamicSharedMemorySize, GDSM);

    cudaMemsetAsync(cntp,  0, (size_t)NB*sizeof(int));
    cudaMemsetAsync(syncp, 0, (SCAN_BLK+1)*sizeof(int));
    const int PREP_BLK = (LL*D*KTOT + 255)/256;          // 1728
    k_count_gather_prep<<<12500 + PREP_BLK, 256>>>(et, dst, x, emb, w_rel, w_root); // k1
    k_scan<<<SCAN_BLK, 256>>>();                         // k2
    k_partition<<<6250, 256>>>(src, dst, et);            // k3
    const int GB = (NN + 127) / 128;                     // 391 tiles
    const size_t LW = (size_t)D*KTOT;
    // layer 0: hA -> hB; layer 1: hB -> hA (+hB); layer 2: hA -> out (+hA)
    k_agg<<<NN, 256>>>(hA);                              // k4 <- profiled
    k_gemm_ln<<<GB, 256, GDSM>>>(Bthi,        Btlo,        bias,       gamma,       beta,       nullptr, hB);
    k_agg<<<NN, 256>>>(hB);
    k_gemm_ln<<<GB, 256, GDSM>>>(Bthi + LW,   Btlo + LW,   bias + D,   gamma + D,   beta + D,   hB,      hA);
    k_agg<<<NN, 256>>>(hA);
    k_gemm_ln<<<GB, 256, GDSM>>>(Bthi + 2*LW, Btlo + 2*LW, bias + 2*D, gamma + 2*D, beta + 2*D, hA,      out);
}

// round 11
// speedup vs baseline: 1.0176x; 1.0066x over previous
#include <cuda_runtime.h>
#include <math.h>
#include <stdint.h>

#define D    128
#define NN   50000
#define EE   1600000
#define RR   8
#define LL   3
#define NB   (RR*NN)
#define SCAN_BLK 391    /* ceil(NB/1024); all 391 blocks co-resident -> sw grid barrier OK */
#define KTOT 1152       /* 8*128 relation means + 128 root */
#define NCH  36         /* KTOT / 32 */
#define SROW 40         /* smem row stride in uint16 (80B, conflict-free) */
#define PLANEB (128*SROW*2)   /* 10240 B per plane */
#define STAGE2B (4*PLANEB)    /* Ahi+Alo+Bhi+Blo = 40960 B */
#define NSTG  3
#define GDSM  (NSTG*STAGE2B)  /* 122880 */

// ---------------- scratch (static device arrays; no allocation) ----------------
__device__ float    g_hA[NN*D];               // ping
__device__ float    g_hB[NN*D];               // pong
__device__ uint16_t g_Ahi[(size_t)NN*KTOT];   // A operand bf16 hi plane
__device__ uint16_t g_Alo[(size_t)NN*KTOT];   // A operand bf16 lo plane
__device__ uint16_t g_Bthi[LL*D*KTOT];        // weights bf16 hi [l][f][k]
__device__ uint16_t g_Btlo[LL*D*KTOT];        // weights bf16 lo
__device__ float    g_invc[NB];
__device__ int      g_cnt[NB];
__device__ int      g_boff[NB+1];
__device__ int      g_bcur[NB];
__device__ int      g_srcs[EE];
__device__ int      g_sync[SCAN_BLK+2];       // [0..SCAN_BLK): flags, [SCAN_BLK]: bid ctr, [SCAN_BLK+1]: barrier
__device__ int      g_sagg[SCAN_BLK];
__device__ int      g_sinc[SCAN_BLK];

// ---------------- helpers ----------------
__device__ __forceinline__ uint32_t su32(const void* p) {
    uint32_t a;
    asm("{.reg .u64 t; cvta.to.shared.u64 t, %1; cvt.u32.u64 %0, t;}" : "=r"(a) : "l"(p));
    return a;
}
__device__ __forceinline__ void cp16(uint32_t s, const void* g) {
    asm volatile("cp.async.cg.shared.global [%0], [%1], 16;" :: "r"(s), "l"(g));
}
__device__ __forceinline__ void ldsm4(uint32_t& r0, uint32_t& r1, uint32_t& r2, uint32_t& r3,
                                      uint32_t addr) {
    asm volatile("ldmatrix.sync.aligned.m8n8.x4.shared.b16 {%0,%1,%2,%3}, [%4];"
                 : "=r"(r0), "=r"(r1), "=r"(r2), "=r"(r3) : "r"(addr));
}
// split (v0,v1) into packed bf16x2 hi and lo (elem k in low half, k+1 in high)
__device__ __forceinline__ void bsplit2(float v0, float v1, uint32_t& hi, uint32_t& lo) {
    asm("cvt.rn.bf16x2.f32 %0, %1, %2;" : "=r"(hi) : "f"(v1), "f"(v0));
    float h0 = __uint_as_float(hi << 16);
    float h1 = __uint_as_float(hi & 0xffff0000u);
    float l0 = v0 - h0, l1 = v1 - h1;
    asm("cvt.rn.bf16x2.f32 %0, %1, %2;" : "=r"(lo) : "f"(l1), "f"(l0));
}
__device__ __forceinline__ void mma_bf16(float* c, const uint32_t* a, const uint32_t* b) {
    asm volatile(
        "mma.sync.aligned.m16n8k16.row.col.f32.bf16.bf16.f32 "
        "{%0,%1,%2,%3},{%4,%5,%6,%7},{%8,%9},{%0,%1,%2,%3};"
        : "+f"(c[0]), "+f"(c[1]), "+f"(c[2]), "+f"(c[3])
        : "r"(a[0]), "r"(a[1]), "r"(a[2]), "r"(a[3]), "r"(b[0]), "r"(b[1]));
}

// ------- kernel 1: edge count + node gather + weight split-prep (one grid) -------
__global__ void k_count_gather_prep(const int* __restrict__ et, const int* __restrict__ dst,
                                    const int* __restrict__ x, const float* __restrict__ emb,
                                    const float* __restrict__ w_rel, const float* __restrict__ w_root) {
    int b = blockIdx.x;
    if (b < 6250) {
        int e = b*256 + threadIdx.x;
        if (e < EE) atomicAdd(&g_cnt[et[e]*NN + dst[e]], 1);
    } else if (b < 12500) {
        int i = (b - 6250)*256 + threadIdx.x;
        if (i < NN*32) {
            int row = i >> 5, c = i & 31;
            ((float4*)g_hA)[i] = ((const float4*)emb)[(long long)x[row]*32 + c];
        }
    } else {
        int i = (b - 12500)*256 + threadIdx.x;
        if (i >= LL*D*KTOT) return;
        int l = i / (D*KTOT);
        int rem = i - l*D*KTOT;
        int f = rem / KTOT;
        int k = rem - f*KTOT;
        float v;
        if (k < RR*D) {
            int r = k >> 7, dd = k & 127;
            v = w_rel[(((size_t)(l*RR + r))*D + dd)*D + f];
        } else {
            int dd = k - RR*D;
            v = w_root[((size_t)l*D + dd)*D + f];
        }
        uint32_t hb;
        asm("cvt.rn.bf16x2.f32 %0, %1, %2;" : "=r"(hb) : "f"(0.f), "f"(v));
        float hf = __uint_as_float(hb << 16);
        float lf = v - hf;
        uint32_t lb;
        asm("cvt.rn.bf16x2.f32 %0, %1, %2;" : "=r"(lb) : "f"(0.f), "f"(lf));
        g_Bthi[i] = (uint16_t)(hb & 0xffff);
        g_Btlo[i] = (uint16_t)(lb & 0xffff);
    }
}

// ------- kernel 2: scan (decoupled lookback) + sw grid barrier + partition -------
__global__ void k_scan_part(const int* __restrict__ src, const int* __restrict__ dst,
                            const int* __restrict__ et) {
    __shared__ int s_bid, s_excl;
    __shared__ int ws[8];
    int t = threadIdx.x;
    if (t == 0) s_bid = atomicAdd(&g_sync[SCAN_BLK], 1);
    __syncthreads();
    int bid = s_bid;
    int base = bid*1024 + t*4;
    int c[4]; int tsum = 0;
    #pragma unroll
    for (int j = 0; j < 4; j++) { int i = base + j; c[j] = (i < NB) ? g_cnt[i] : 0; tsum += c[j]; }
    int x = tsum;
    int lane = t & 31, wid = t >> 5;
    #pragma unroll
    for (int o = 1; o < 32; o <<= 1) { int y = __shfl_up_sync(0xffffffffu, x, o); if (lane >= o) x += y; }
    if (lane == 31) ws[wid] = x;
    __syncthreads();
    if (t == 0) {
        int tot = 0;
        #pragma unroll
        for (int w = 0; w < 8; w++) tot += ws[w];
        g_sagg[bid] = tot;
        __threadfence();
        atomicExch(&g_sync[bid], 1);
        int excl = 0;
        for (int j = bid - 1; j >= 0; ) {
            int f;
            do { f = atomicAdd(&g_sync[j], 0); } while (f == 0);
            if (f == 2) { excl += atomicAdd(&g_sinc[j], 0); break; }
            excl += atomicAdd(&g_sagg[j], 0);
            j--;
        }
        g_sinc[bid] = excl + tot;
        __threadfence();
        atomicExch(&g_sync[bid], 2);
        s_excl = excl;
        if (bid == 0) g_boff[NB] = EE;
    }
    __syncthreads();
    int pre = s_excl;
    for (int w = 0; w < wid; w++) pre += ws[w];
    int off = pre + x - tsum;
    #pragma unroll
    for (int j = 0; j < 4; j++) {
        int i = base + j;
        if (i < NB) {
            g_boff[i] = off; g_bcur[i] = off; off += c[j];
            g_invc[i] = 1.0f / fmaxf((float)c[j], 1.0f);
        }
    }

    // ---- software grid barrier (all SCAN_BLK blocks co-resident) ----
    __threadfence();
    __syncthreads();
    if (t == 0) {
        atomicAdd(&g_sync[SCAN_BLK+1], 1);
        while (atomicAdd(&g_sync[SCAN_BLK+1], 0) < SCAN_BLK) { }
    }
    __syncthreads();

    // ---- partition phase: stride all edges over this grid ----
    for (int e = bid*256 + t; e < EE; e += SCAN_BLK*256) {
        int b = et[e]*NN + dst[e];
        int p = atomicAdd(&g_bcur[b], 1);
        g_srcs[p] = src[e];
    }
}

// ------- kernel 3: 8 relation means + root -> split bf16 planes ------------------
__global__ void k_agg(const float* __restrict__ h) {
    int n = blockIdx.x;
    int wid = threadIdx.x >> 5, lane = threadIdx.x & 31;
    int b = wid*NN + n;
    int beg = g_boff[b], end = g_boff[b+1];
    const float4* h4 = (const float4*)h;
    float4 acc = make_float4(0.f, 0.f, 0.f, 0.f);
    int e = beg;
    for (; e + 4 <= end; e += 4) {
        int s0 = g_srcs[e], s1 = g_srcs[e+1], s2 = g_srcs[e+2], s3 = g_srcs[e+3];
        float4 v0 = h4[s0*32 + lane];
        float4 v1 = h4[s1*32 + lane];
        float4 v2 = h4[s2*32 + lane];
        float4 v3 = h4[s3*32 + lane];
        acc.x += v0.x + v1.x + v2.x + v3.x;
        acc.y += v0.y + v1.y + v2.y + v3.y;
        acc.z += v0.z + v1.z + v2.z + v3.z;
        acc.w += v0.w + v1.w + v2.w + v3.w;
    }
    for (; e < end; e++) {
        float4 v = h4[g_srcs[e]*32 + lane];
        acc.x += v.x; acc.y += v.y; acc.z += v.z; acc.w += v.w;
    }
    float sc = g_invc[b];
    acc.x *= sc; acc.y *= sc; acc.z *= sc; acc.w *= sc;
    uint32_t h0, l0, h1, l1;
    bsplit2(acc.x, acc.y, h0, l0);
    bsplit2(acc.z, acc.w, h1, l1);
    int idx = n*KTOT + wid*D + lane*4;     // < 57.6M, fits int
    *(uint2*)&g_Ahi[idx] = make_uint2(h0, h1);
    *(uint2*)&g_Alo[idx] = make_uint2(l0, l1);
    if (threadIdx.x < 32) {
        float4 v = h4[n*32 + threadIdx.x];
        bsplit2(v.x, v.y, h0, l0);
        bsplit2(v.z, v.w, h1, l1);
        int ridx = n*KTOT + RR*D + threadIdx.x*4;
        *(uint2*)&g_Ahi[ridx] = make_uint2(h0, h1);
        *(uint2*)&g_Alo[ridx] = make_uint2(l0, l1);
    }
}

// ------- kernel 4 (profiled): bf16x3 mma GEMM + fused bias/LN/ReLU/residual -----
__global__ void __launch_bounds__(256, 1) k_gemm_ln(
    const uint16_t* __restrict__ Bhi, const uint16_t* __restrict__ Blo,
    const float* __restrict__ bias, const float* __restrict__ gamma,
    const float* __restrict__ beta, const float* __restrict__ hprev,
    float* __restrict__ dst)
{
    extern __shared__ float smf[];
    int tid = threadIdx.x, wid = tid >> 5, lane = tid & 31;
    int row0 = blockIdx.x * 128;
    int warp_m = (wid >> 2) * 64;       // 0 or 64
    int warp_n = (wid & 3) * 32;        // 0,32,64,96
    int grp = lane >> 2, qid = lane & 3;
    uint32_t sbase = su32(smf);

    // ldmatrix per-thread offsets (bytes)
    uint32_t aoff = (uint32_t)(((warp_m + (lane & 15))*SROW + ((lane >> 4) << 3)) * 2);
    uint32_t boff = (uint32_t)(((warp_n + ((lane >> 4) << 3) + (lane & 7))*SROW
                                + (((lane >> 3) & 1) << 3)) * 2);

    float c[4][4][4];
    #pragma unroll
    for (int i = 0; i < 4; i++)
        #pragma unroll
        for (int j = 0; j < 4; j++)
            #pragma unroll
            for (int q = 0; q < 4; q++) c[i][j][q] = 0.f;

    auto load_chunk = [&](int it, int s) {
        const int kb = it * 32;
        uint32_t st = sbase + (uint32_t)s*STAGE2B;
        #pragma unroll
        for (int j = 0; j < 2; j++) {
            int slot = tid + j*256;           // 0..511
            int row = slot >> 2, seg = slot & 3;
            uint32_t soff = (uint32_t)(row*(SROW*2) + seg*16);
            int gm = row0 + row; if (gm >= NN) gm = NN - 1;   // clamp (never stored)
            size_t ga = (size_t)gm*KTOT + kb + seg*8;
            size_t gb = (size_t)row*KTOT + kb + seg*8;
            cp16(st + soff,             g_Ahi + ga);
            cp16(st + PLANEB + soff,    g_Alo + ga);
            cp16(st + 2*PLANEB + soff,  Bhi + gb);
            cp16(st + 3*PLANEB + soff,  Blo + gb);
        }
        asm volatile("cp.async.commit_group;" ::: "memory");
    };

    load_chunk(0, 0);
    load_chunk(1, 1);

    for (int it = 0; it < NCH; it++) {
        int s = it % NSTG;
        if (it < NCH-1) asm volatile("cp.async.wait_group 1;" ::: "memory");
        else            asm volatile("cp.async.wait_group 0;" ::: "memory");
        __syncthreads();

        if (it + 2 < NCH) load_chunk(it + 2, (it + 2) % NSTG);

        uint32_t st = sbase + (uint32_t)s*STAGE2B;
        #pragma unroll
        for (int kk = 0; kk < 32; kk += 16) {
            uint32_t ah[4][4], al[4][4], bh[4][2], bl[4][2];
            uint32_t aA = st + aoff + (uint32_t)(kk*2);
            uint32_t aB = st + 2*PLANEB + boff + (uint32_t)(kk*2);
            #pragma unroll
            for (int i = 0; i < 4; i++) {
                ldsm4(ah[i][0], ah[i][1], ah[i][2], ah[i][3], aA + (uint32_t)(i*1280));
                ldsm4(al[i][0], al[i][1], al[i][2], al[i][3], aA + PLANEB + (uint32_t)(i*1280));
            }
            ldsm4(bh[0][0], bh[0][1], bh[1][0], bh[1][1], aB);
            ldsm4(bh[2][0], bh[2][1], bh[3][0], bh[3][1], aB + 1280u);
            ldsm4(bl[0][0], bl[0][1], bl[1][0], bl[1][1], aB + PLANEB);
            ldsm4(bl[2][0], bl[2][1], bl[3][0], bl[3][1], aB + PLANEB + 1280u);
            #pragma unroll
            for (int i = 0; i < 4; i++)
                #pragma unroll
                for (int j = 0; j < 4; j++) {
                    mma_bf16(c[i][j], al[i], bh[j]);
                    mma_bf16(c[i][j], ah[i], bl[j]);
                    mma_bf16(c[i][j], ah[i], bh[j]);
                }
        }
    }
    __syncthreads();

    // ---- fused epilogue: bias + LayerNorm + ReLU + residual ----
    float* redSum = smf;            // [128][4]
    float* redSq  = smf + 512;      // [128][4]
    float* s_mu   = smf + 1024;     // [128]
    float* s_rs   = smf + 1152;     // [128]
    int wn = wid & 3;

    float2 gset[4], bset[4];
    #pragma unroll
    for (int j = 0; j < 4; j++) {
        int col = warp_n + j*8 + qid*2;
        gset[j] = *(const float2*)&gamma[col];
        bset[j] = *(const float2*)&beta[col];
    }
    #pragma unroll
    for (int i = 0; i < 4; i++) {
        float s0 = 0.f, q0 = 0.f, s1 = 0.f, q1 = 0.f;
        #pragma unroll
        for (int j = 0; j < 4; j++) {
            int col = warp_n + j*8 + qid*2;
            float bx = bias[col], by = bias[col+1];
            c[i][j][0] += bx; c[i][j][1] += by;
            c[i][j][2] += bx; c[i][j][3] += by;
            s0 += c[i][j][0] + c[i][j][1];
            q0 += c[i][j][0]*c[i][j][0] + c[i][j][1]*c[i][j][1];
            s1 += c[i][j][2] + c[i][j][3];
            q1 += c[i][j][2]*c[i][j][2] + c[i][j][3]*c[i][j][3];
        }
        #pragma unroll
        for (int o = 1; o <= 2; o <<= 1) {
            s0 += __shfl_xor_sync(0xffffffffu, s0, o);
            q0 += __shfl_xor_sync(0xffffffffu, q0, o);
            s1 += __shfl_xor_sync(0xffffffffu, s1, o);
            q1 += __shfl_xor_sync(0xffffffffu, q1, o);
        }
        if (qid == 0) {
            int r0 = warp_m + i*16 + grp;
            redSum[r0*4 + wn] = s0;  redSq[r0*4 + wn] = q0;
            redSum[(r0+8)*4 + wn] = s1;  redSq[(r0+8)*4 + wn] = q1;
        }
    }
    __syncthreads();
    if (tid < 128) {
        float s = redSum[tid*4+0] + redSum[tid*4+1] + redSum[tid*4+2] + redSum[tid*4+3];
        float q = redSq[tid*4+0] + redSq[tid*4+1] + redSq[tid*4+2] + redSq[tid*4+3];
        float mu = s * (1.0f/D);
        float var = q * (1.0f/D) - mu*mu;
        s_mu[tid] = mu;
        s_rs[tid] = rsqrtf(var + 1e-5f);
    }
    __syncthreads();

    #pragma unroll
    for (int i = 0; i < 4; i++) {
        int lr0 = warp_m + i*16 + grp;
        int lr1 = lr0 + 8;
        float mu0 = s_mu[lr0], rs0 = s_rs[lr0];
        float mu1 = s_mu[lr1], rs1 = s_rs[lr1];
        int gm0 = row0 + lr0, gm1 = row0 + lr1;
        #pragma unroll
        for (int j = 0; j < 4; j++) {
            int col = warp_n + j*8 + qid*2;
            if (gm0 < NN) {
                float y0 = fmaxf((c[i][j][0]-mu0)*rs0*gset[j].x + bset[j].x, 0.f);
                float y1 = fmaxf((c[i][j][1]-mu0)*rs0*gset[j].y + bset[j].y, 0.f);
                if (hprev) {
                    const float2 p = *(const float2*)&hprev[(size_t)gm0*D + col];
                    y0 += p.x; y1 += p.y;
                }
                *(float2*)&dst[(size_t)gm0*D + col] = make_float2(y0, y1);
            }
            if (gm1 < NN) {
                float y0 = fmaxf((c[i][j][2]-mu1)*rs1*gset[j].x + bset[j].x, 0.f);
                float y1 = fmaxf((c[i][j][3]-mu1)*rs1*gset[j].y + bset[j].y, 0.f);
                if (hprev) {
                    const float2 p = *(const float2*)&hprev[(size_t)gm1*D + col];
                    y0 += p.x; y1 += p.y;
                }
                *(float2*)&dst[(size_t)gm1*D + col] = make_float2(y0, y1);
            }
        }
    }
}

// ---------------- launcher ----------------
extern "C" void kernel_launch(void* const* d_in, const int* in_sizes, int n_in,
                              void* d_out, int out_size)
{
    const int*   x      = (const int*)d_in[0];
    const int*   ei     = (const int*)d_in[1];
    const int*   et     = (const int*)d_in[2];
    const float* emb    = (const float*)d_in[3];
    const float* w_rel  = (const float*)d_in[4];
    const float* w_root = (const float*)d_in[5];
    const float* bias   = (const float*)d_in[6];
    const float* gamma  = (const float*)d_in[7];
    const float* beta   = (const float*)d_in[8];
    float* out = (float*)d_out;
    const int* src = ei;
    const int* dst = ei + EE;

    float *hA, *hB;
    uint16_t *Bthi, *Btlo;
    int *cntp, *syncp;
    cudaGetSymbolAddress((void**)&hA,    g_hA);
    cudaGetSymbolAddress((void**)&hB,    g_hB);
    cudaGetSymbolAddress((void**)&Bthi,  g_Bthi);
    cudaGetSymbolAddress((void**)&Btlo,  g_Btlo);
    cudaGetSymbolAddress((void**)&cntp,  g_cnt);
    cudaGetSymbolAddress((void**)&syncp, g_sync);

    cudaFuncSetAttribute(k_gemm_ln, cudaFuncAttributeMaxDynamicSharedMemorySize, GDSM);

    cudaMemsetAsync(cntp,  0, (size_t)NB*sizeof(int));
    cudaMemsetAsync(syncp, 0, (SCAN_BLK+2)*sizeof(int));
    const int PREP_BLK = (LL*D*KTOT + 255)/256;          // 1728
    k_count_gather_prep<<<12500 + PREP_BLK, 256>>>(et, dst, x, emb, w_rel, w_root); // k1
    k_scan_part<<<SCAN_BLK, 256>>>(src, dst, et);        // k2 (scan + barrier + partition)
    const int GB = (NN + 127) / 128;                     // 391 tiles
    const size_t LW = (size_t)D*KTOT;
    // layer 0: hA -> hB; layer 1: hB -> hA (+hB); layer 2: hA -> out (+hA)
    k_agg<<<NN, 256>>>(hA);                              // k3
    k_gemm_ln<<<GB, 256, GDSM>>>(Bthi,        Btlo,        bias,       gamma,       beta,       nullptr, hB);  // k4 <- profiled
    k_agg<<<NN, 256>>>(hB);
    k_gemm_ln<<<GB, 256, GDSM>>>(Bthi + LW,   Btlo + LW,   bias + D,   gamma + D,   beta + D,   hB,      hA);
    k_agg<<<NN, 256>>>(hA);
    k_gemm_ln<<<GB, 256, GDSM>>>(Bthi + 2*LW, Btlo + 2*LW, bias + 2*D, gamma + 2*D, beta + 2*D, hA,      out);
}

// round 12
// speedup vs baseline: 1.1292x; 1.1097x over previous
#include <cuda_runtime.h>
#include <math.h>
#include <stdint.h>

#define D    128
#define NN   50000
#define EE   1600000
#define RR   8
#define LL   3
#define NB   (RR*NN)
#define SCAN_BLK 391    /* ceil(NB/1024); all 391 blocks co-resident -> sw grid barrier OK */
#define KTOT 1152       /* 8*128 relation means + 128 root */
#define NCH  36         /* KTOT / 32 */
#define SROW 40         /* smem row stride in uint16 (80B, conflict-free) */
#define PLANEB (128*SROW*2)   /* 10240 B per plane */
#define STAGE2B (4*PLANEB)    /* Ahi+Alo+Bhi+Blo = 40960 B */
#define NSTG  2
#define GDSM  (NSTG*STAGE2B)  /* 81920; 2 CTAs/SM = 163840 < 228KB */

// ---------------- scratch (static device arrays; no allocation) ----------------
__device__ float    g_hA[NN*D];               // ping
__device__ float    g_hB[NN*D];               // pong
__device__ uint16_t g_Ahi[(size_t)NN*KTOT];   // A operand bf16 hi plane
__device__ uint16_t g_Alo[(size_t)NN*KTOT];   // A operand bf16 lo plane
__device__ uint16_t g_Bthi[LL*D*KTOT];        // weights bf16 hi [l][f][k]
__device__ uint16_t g_Btlo[LL*D*KTOT];        // weights bf16 lo
__device__ float    g_invc[NB];
__device__ int      g_cnt[NB];
__device__ int      g_boff[NB+1];
__device__ int      g_bcur[NB];
__device__ int      g_srcs[EE];
__device__ int      g_sync[SCAN_BLK+2];       // [0..SCAN_BLK): flags, [SCAN_BLK]: bid ctr, [SCAN_BLK+1]: barrier
__device__ int      g_sagg[SCAN_BLK];
__device__ int      g_sinc[SCAN_BLK];

// ---------------- helpers ----------------
__device__ __forceinline__ uint32_t su32(const void* p) {
    uint32_t a;
    asm("{.reg .u64 t; cvta.to.shared.u64 t, %1; cvt.u32.u64 %0, t;}" : "=r"(a) : "l"(p));
    return a;
}
__device__ __forceinline__ void cp16(uint32_t s, const void* g) {
    asm volatile("cp.async.cg.shared.global [%0], [%1], 16;" :: "r"(s), "l"(g));
}
__device__ __forceinline__ void ldsm4(uint32_t& r0, uint32_t& r1, uint32_t& r2, uint32_t& r3,
                                      uint32_t addr) {
    asm volatile("ldmatrix.sync.aligned.m8n8.x4.shared.b16 {%0,%1,%2,%3}, [%4];"
                 : "=r"(r0), "=r"(r1), "=r"(r2), "=r"(r3) : "r"(addr));
}
// split (v0,v1) into packed bf16x2 hi and lo (elem k in low half, k+1 in high)
__device__ __forceinline__ void bsplit2(float v0, float v1, uint32_t& hi, uint32_t& lo) {
    asm("cvt.rn.bf16x2.f32 %0, %1, %2;" : "=r"(hi) : "f"(v1), "f"(v0));
    float h0 = __uint_as_float(hi << 16);
    float h1 = __uint_as_float(hi & 0xffff0000u);
    float l0 = v0 - h0, l1 = v1 - h1;
    asm("cvt.rn.bf16x2.f32 %0, %1, %2;" : "=r"(lo) : "f"(l1), "f"(l0));
}
__device__ __forceinline__ void mma_bf16(float* c, const uint32_t* a, const uint32_t* b) {
    asm volatile(
        "mma.sync.aligned.m16n8k16.row.col.f32.bf16.bf16.f32 "
        "{%0,%1,%2,%3},{%4,%5,%6,%7},{%8,%9},{%0,%1,%2,%3};"
        : "+f"(c[0]), "+f"(c[1]), "+f"(c[2]), "+f"(c[3])
        : "r"(a[0]), "r"(a[1]), "r"(a[2]), "r"(a[3]), "r"(b[0]), "r"(b[1]));
}

// ------- kernel 1: edge count + node gather + weight split-prep (one grid) -------
__global__ void k_count_gather_prep(const int* __restrict__ et, const int* __restrict__ dst,
                                    const int* __restrict__ x, const float* __restrict__ emb,
                                    const float* __restrict__ w_rel, const float* __restrict__ w_root) {
    int b = blockIdx.x;
    if (b < 6250) {
        int e = b*256 + threadIdx.x;
        if (e < EE) atomicAdd(&g_cnt[et[e]*NN + dst[e]], 1);
    } else if (b < 12500) {
        int i = (b - 6250)*256 + threadIdx.x;
        if (i < NN*32) {
            int row = i >> 5, c = i & 31;
            ((float4*)g_hA)[i] = ((const float4*)emb)[(long long)x[row]*32 + c];
        }
    } else {
        int i = (b - 12500)*256 + threadIdx.x;
        if (i >= LL*D*KTOT) return;
        int l = i / (D*KTOT);
        int rem = i - l*D*KTOT;
        int f = rem / KTOT;
        int k = rem - f*KTOT;
        float v;
        if (k < RR*D) {
            int r = k >> 7, dd = k & 127;
            v = w_rel[(((size_t)(l*RR + r))*D + dd)*D + f];
        } else {
            int dd = k - RR*D;
            v = w_root[((size_t)l*D + dd)*D + f];
        }
        uint32_t hb;
        asm("cvt.rn.bf16x2.f32 %0, %1, %2;" : "=r"(hb) : "f"(0.f), "f"(v));
        float hf = __uint_as_float(hb << 16);
        float lf = v - hf;
        uint32_t lb;
        asm("cvt.rn.bf16x2.f32 %0, %1, %2;" : "=r"(lb) : "f"(0.f), "f"(lf));
        g_Bthi[i] = (uint16_t)(hb & 0xffff);
        g_Btlo[i] = (uint16_t)(lb & 0xffff);
    }
}

// ------- kernel 2: scan (decoupled lookback) + sw grid barrier + partition -------
__global__ void k_scan_part(const int* __restrict__ src, const int* __restrict__ dst,
                            const int* __restrict__ et) {
    __shared__ int s_bid, s_excl;
    __shared__ int ws[8];
    int t = threadIdx.x;
    if (t == 0) s_bid = atomicAdd(&g_sync[SCAN_BLK], 1);
    __syncthreads();
    int bid = s_bid;
    int base = bid*1024 + t*4;
    int c[4]; int tsum = 0;
    #pragma unroll
    for (int j = 0; j < 4; j++) { int i = base + j; c[j] = (i < NB) ? g_cnt[i] : 0; tsum += c[j]; }
    int x = tsum;
    int lane = t & 31, wid = t >> 5;
    #pragma unroll
    for (int o = 1; o < 32; o <<= 1) { int y = __shfl_up_sync(0xffffffffu, x, o); if (lane >= o) x += y; }
    if (lane == 31) ws[wid] = x;
    __syncthreads();
    if (t == 0) {
        int tot = 0;
        #pragma unroll
        for (int w = 0; w < 8; w++) tot += ws[w];
        g_sagg[bid] = tot;
        __threadfence();
        atomicExch(&g_sync[bid], 1);
        int excl = 0;
        for (int j = bid - 1; j >= 0; ) {
            int f;
            do { f = atomicAdd(&g_sync[j], 0); } while (f == 0);
            if (f == 2) { excl += atomicAdd(&g_sinc[j], 0); break; }
            excl += atomicAdd(&g_sagg[j], 0);
            j--;
        }
        g_sinc[bid] = excl + tot;
        __threadfence();
        atomicExch(&g_sync[bid], 2);
        s_excl = excl;
        if (bid == 0) g_boff[NB] = EE;
    }
    __syncthreads();
    int pre = s_excl;
    for (int w = 0; w < wid; w++) pre += ws[w];
    int off = pre + x - tsum;
    #pragma unroll
    for (int j = 0; j < 4; j++) {
        int i = base + j;
        if (i < NB) {
            g_boff[i] = off; g_bcur[i] = off; off += c[j];
            g_invc[i] = 1.0f / fmaxf((float)c[j], 1.0f);
        }
    }

    // ---- software grid barrier (all SCAN_BLK blocks co-resident) ----
    __threadfence();
    __syncthreads();
    if (t == 0) {
        atomicAdd(&g_sync[SCAN_BLK+1], 1);
        while (atomicAdd(&g_sync[SCAN_BLK+1], 0) < SCAN_BLK) { }
    }
    __syncthreads();

    // ---- partition phase: stride all edges over this grid ----
    for (int e = bid*256 + t; e < EE; e += SCAN_BLK*256) {
        int b = et[e]*NN + dst[e];
        int p = atomicAdd(&g_bcur[b], 1);
        g_srcs[p] = src[e];
    }
}

// ------- kernel 3: 8 relation means + root -> split bf16 planes ------------------
__global__ void k_agg(const float* __restrict__ h) {
    int n = blockIdx.x;
    int wid = threadIdx.x >> 5, lane = threadIdx.x & 31;
    int b = wid*NN + n;
    int beg = g_boff[b], end = g_boff[b+1];
    const float4* h4 = (const float4*)h;
    float4 acc = make_float4(0.f, 0.f, 0.f, 0.f);
    int e = beg;
    for (; e + 4 <= end; e += 4) {
        int s0 = g_srcs[e], s1 = g_srcs[e+1], s2 = g_srcs[e+2], s3 = g_srcs[e+3];
        float4 v0 = h4[s0*32 + lane];
        float4 v1 = h4[s1*32 + lane];
        float4 v2 = h4[s2*32 + lane];
        float4 v3 = h4[s3*32 + lane];
        acc.x += v0.x + v1.x + v2.x + v3.x;
        acc.y += v0.y + v1.y + v2.y + v3.y;
        acc.z += v0.z + v1.z + v2.z + v3.z;
        acc.w += v0.w + v1.w + v2.w + v3.w;
    }
    for (; e < end; e++) {
        float4 v = h4[g_srcs[e]*32 + lane];
        acc.x += v.x; acc.y += v.y; acc.z += v.z; acc.w += v.w;
    }
    float sc = g_invc[b];
    acc.x *= sc; acc.y *= sc; acc.z *= sc; acc.w *= sc;
    uint32_t h0, l0, h1, l1;
    bsplit2(acc.x, acc.y, h0, l0);
    bsplit2(acc.z, acc.w, h1, l1);
    int idx = n*KTOT + wid*D + lane*4;     // < 57.6M, fits int
    *(uint2*)&g_Ahi[idx] = make_uint2(h0, h1);
    *(uint2*)&g_Alo[idx] = make_uint2(l0, l1);
    if (threadIdx.x < 32) {
        float4 v = h4[n*32 + threadIdx.x];
        bsplit2(v.x, v.y, h0, l0);
        bsplit2(v.z, v.w, h1, l1);
        int ridx = n*KTOT + RR*D + threadIdx.x*4;
        *(uint2*)&g_Ahi[ridx] = make_uint2(h0, h1);
        *(uint2*)&g_Alo[ridx] = make_uint2(l0, l1);
    }
}

// ------- kernel 4 (profiled): bf16x3 mma GEMM, 2 CTAs/SM + fused LN epilogue -----
__global__ void __launch_bounds__(256, 2) k_gemm_ln(
    const uint16_t* __restrict__ Bhi, const uint16_t* __restrict__ Blo,
    const float* __restrict__ bias, const float* __restrict__ gamma,
    const float* __restrict__ beta, const float* __restrict__ hprev,
    float* __restrict__ dst)
{
    extern __shared__ float smf[];
    int tid = threadIdx.x, wid = tid >> 5, lane = tid & 31;
    int row0 = blockIdx.x * 128;
    int warp_m = (wid >> 2) * 64;       // 0 or 64
    int warp_n = (wid & 3) * 32;        // 0,32,64,96
    int grp = lane >> 2, qid = lane & 3;
    uint32_t sbase = su32(smf);

    // ldmatrix per-thread offsets (bytes)
    uint32_t aoff = (uint32_t)(((warp_m + (lane & 15))*SROW + ((lane >> 4) << 3)) * 2);
    uint32_t boff = (uint32_t)(((warp_n + ((lane >> 4) << 3) + (lane & 7))*SROW
                                + (((lane >> 3) & 1) << 3)) * 2);

    float c[4][4][4];
    #pragma unroll
    for (int i = 0; i < 4; i++)
        #pragma unroll
        for (int j = 0; j < 4; j++)
            #pragma unroll
            for (int q = 0; q < 4; q++) c[i][j][q] = 0.f;

    auto load_chunk = [&](int it, int s) {
        const int kb = it * 32;
        uint32_t st = sbase + (uint32_t)s*STAGE2B;
        #pragma unroll
        for (int j = 0; j < 2; j++) {
            int slot = tid + j*256;           // 0..511
            int row = slot >> 2, seg = slot & 3;
            uint32_t soff = (uint32_t)(row*(SROW*2) + seg*16);
            int gm = row0 + row; if (gm >= NN) gm = NN - 1;   // clamp (never stored)
            size_t ga = (size_t)gm*KTOT + kb + seg*8;
            size_t gb = (size_t)row*KTOT + kb + seg*8;
            cp16(st + soff,             g_Ahi + ga);
            cp16(st + PLANEB + soff,    g_Alo + ga);
            cp16(st + 2*PLANEB + soff,  Bhi + gb);
            cp16(st + 3*PLANEB + soff,  Blo + gb);
        }
        asm volatile("cp.async.commit_group;" ::: "memory");
    };

    load_chunk(0, 0);
    load_chunk(1, 1);

    for (int it = 0; it < NCH; it++) {
        int s = it & 1;
        if (it < NCH-1) asm volatile("cp.async.wait_group 1;" ::: "memory");
        else            asm volatile("cp.async.wait_group 0;" ::: "memory");
        __syncthreads();

        uint32_t st = sbase + (uint32_t)s*STAGE2B;
        #pragma unroll
        for (int kk = 0; kk < 32; kk += 16) {
            uint32_t ah[4][4], al[4][4], bh[4][2], bl[4][2];
            uint32_t aA = st + aoff + (uint32_t)(kk*2);
            uint32_t aB = st + 2*PLANEB + boff + (uint32_t)(kk*2);
            #pragma unroll
            for (int i = 0; i < 4; i++) {
                ldsm4(ah[i][0], ah[i][1], ah[i][2], ah[i][3], aA + (uint32_t)(i*1280));
                ldsm4(al[i][0], al[i][1], al[i][2], al[i][3], aA + PLANEB + (uint32_t)(i*1280));
            }
            ldsm4(bh[0][0], bh[0][1], bh[1][0], bh[1][1], aB);
            ldsm4(bh[2][0], bh[2][1], bh[3][0], bh[3][1], aB + 1280u);
            ldsm4(bl[0][0], bl[0][1], bl[1][0], bl[1][1], aB + PLANEB);
            ldsm4(bl[2][0], bl[2][1], bl[3][0], bl[3][1], aB + PLANEB + 1280u);
            #pragma unroll
            for (int i = 0; i < 4; i++)
                #pragma unroll
                for (int j = 0; j < 4; j++) {
                    mma_bf16(c[i][j], al[i], bh[j]);
                    mma_bf16(c[i][j], ah[i], bl[j]);
                    mma_bf16(c[i][j], ah[i], bh[j]);
                }
        }
        __syncthreads();
        if (it + 2 < NCH) load_chunk(it + 2, s);
    }
    __syncthreads();

    // ---- fused epilogue: bias + LayerNorm + ReLU + residual ----
    float* redSum = smf;            // [128][4]
    float* redSq  = smf + 512;      // [128][4]
    float* s_mu   = smf + 1024;     // [128]
    float* s_rs   = smf + 1152;     // [128]
    int wn = wid & 3;

    float2 gset[4], bset[4];
    #pragma unroll
    for (int j = 0; j < 4; j++) {
        int col = warp_n + j*8 + qid*2;
        gset[j] = *(const float2*)&gamma[col];
        bset[j] = *(const float2*)&beta[col];
    }
    #pragma unroll
    for (int i = 0; i < 4; i++) {
        float s0 = 0.f, q0 = 0.f, s1 = 0.f, q1 = 0.f;
        #pragma unroll
        for (int j = 0; j < 4; j++) {
            int col = warp_n + j*8 + qid*2;
            float bx = bias[col], by = bias[col+1];
            c[i][j][0] += bx; c[i][j][1] += by;
            c[i][j][2] += bx; c[i][j][3] += by;
            s0 += c[i][j][0] + c[i][j][1];
            q0 += c[i][j][0]*c[i][j][0] + c[i][j][1]*c[i][j][1];
            s1 += c[i][j][2] + c[i][j][3];
            q1 += c[i][j][2]*c[i][j][2] + c[i][j][3]*c[i][j][3];
        }
        #pragma unroll
        for (int o = 1; o <= 2; o <<= 1) {
            s0 += __shfl_xor_sync(0xffffffffu, s0, o);
            q0 += __shfl_xor_sync(0xffffffffu, q0, o);
            s1 += __shfl_xor_sync(0xffffffffu, s1, o);
            q1 += __shfl_xor_sync(0xffffffffu, q1, o);
        }
        if (qid == 0) {
            int r0 = warp_m + i*16 + grp;
            redSum[r0*4 + wn] = s0;  redSq[r0*4 + wn] = q0;
            redSum[(r0+8)*4 + wn] = s1;  redSq[(r0+8)*4 + wn] = q1;
        }
    }
    __syncthreads();
    if (tid < 128) {
        float s = redSum[tid*4+0] + redSum[tid*4+1] + redSum[tid*4+2] + redSum[tid*4+3];
        float q = redSq[tid*4+0] + redSq[tid*4+1] + redSq[tid*4+2] + redSq[tid*4+3];
        float mu = s * (1.0f/D);
        float var = q * (1.0f/D) - mu*mu;
        s_mu[tid] = mu;
        s_rs[tid] = rsqrtf(var + 1e-5f);
    }
    __syncthreads();

    #pragma unroll
    for (int i = 0; i < 4; i++) {
        int lr0 = warp_m + i*16 + grp;
        int lr1 = lr0 + 8;
        float mu0 = s_mu[lr0], rs0 = s_rs[lr0];
        float mu1 = s_mu[lr1], rs1 = s_rs[lr1];
        int gm0 = row0 + lr0, gm1 = row0 + lr1;
        #pragma unroll
        for (int j = 0; j < 4; j++) {
            int col = warp_n + j*8 + qid*2;
            if (gm0 < NN) {
                float y0 = fmaxf((c[i][j][0]-mu0)*rs0*gset[j].x + bset[j].x, 0.f);
                float y1 = fmaxf((c[i][j][1]-mu0)*rs0*gset[j].y + bset[j].y, 0.f);
                if (hprev) {
                    const float2 p = *(const float2*)&hprev[(size_t)gm0*D + col];
                    y0 += p.x; y1 += p.y;
                }
                *(float2*)&dst[(size_t)gm0*D + col] = make_float2(y0, y1);
            }
            if (gm1 < NN) {
                float y0 = fmaxf((c[i][j][2]-mu1)*rs1*gset[j].x + bset[j].x, 0.f);
                float y1 = fmaxf((c[i][j][3]-mu1)*rs1*gset[j].y + bset[j].y, 0.f);
                if (hprev) {
                    const float2 p = *(const float2*)&hprev[(size_t)gm1*D + col];
                    y0 += p.x; y1 += p.y;
                }
                *(float2*)&dst[(size_t)gm1*D + col] = make_float2(y0, y1);
            }
        }
    }
}

// ---------------- launcher ----------------
extern "C" void kernel_launch(void* const* d_in, const int* in_sizes, int n_in,
                              void* d_out, int out_size)
{
    const int*   x      = (const int*)d_in[0];
    const int*   ei     = (const int*)d_in[1];
    const int*   et     = (const int*)d_in[2];
    const float* emb    = (const float*)d_in[3];
    const float* w_rel  = (const float*)d_in[4];
    const float* w_root = (const float*)d_in[5];
    const float* bias   = (const float*)d_in[6];
    const float* gamma  = (const float*)d_in[7];
    const float* beta   = (const float*)d_in[8];
    float* out = (float*)d_out;
    const int* src = ei;
    const int* dst = ei + EE;

    float *hA, *hB;
    uint16_t *Bthi, *Btlo;
    int *cntp, *syncp;
    cudaGetSymbolAddress((void**)&hA,    g_hA);
    cudaGetSymbolAddress((void**)&hB,    g_hB);
    cudaGetSymbolAddress((void**)&Bthi,  g_Bthi);
    cudaGetSymbolAddress((void**)&Btlo,  g_Btlo);
    cudaGetSymbolAddress((void**)&cntp,  g_cnt);
    cudaGetSymbolAddress((void**)&syncp, g_sync);

    cudaFuncSetAttribute(k_gemm_ln, cudaFuncAttributeMaxDynamicSharedMemorySize, GDSM);

    cudaMemsetAsync(cntp,  0, (size_t)NB*sizeof(int));
    cudaMemsetAsync(syncp, 0, (SCAN_BLK+2)*sizeof(int));
    const int PREP_BLK = (LL*D*KTOT + 255)/256;          // 1728
    k_count_gather_prep<<<12500 + PREP_BLK, 256>>>(et, dst, x, emb, w_rel, w_root); // k1
    k_scan_part<<<SCAN_BLK, 256>>>(src, dst, et);        // k2 (scan + barrier + partition)
    const int GB = (NN + 127) / 128;                     // 391 tiles
    const size_t LW = (size_t)D*KTOT;
    // layer 0: hA -> hB; layer 1: hB -> hA (+hB); layer 2: hA -> out (+hA)
    k_agg<<<NN, 256>>>(hA);                              // k3
    k_gemm_ln<<<GB, 256, GDSM>>>(Bthi,        Btlo,        bias,       gamma,       beta,       nullptr, hB);  // k4 <- profiled
    k_agg<<<NN, 256>>>(hB);
    k_gemm_ln<<<GB, 256, GDSM>>>(Bthi + LW,   Btlo + LW,   bias + D,   gamma + D,   beta + D,   hB,      hA);
    k_agg<<<NN, 256>>>(hA);
    k_gemm_ln<<<GB, 256, GDSM>>>(Bthi + 2*LW, Btlo + 2*LW, bias + 2*D, gamma + 2*D, beta + 2*D, hA,      out);
}